// round 2
// baseline (speedup 1.0000x reference)
#include <cuda_runtime.h>
#include <math.h>

#define N_PIX_MAX 4194304
#define N_BINS    350000
#define TAPS      901
#define HALF      450
#define TILE      1024
#define CONV_THREADS 256

// ---------------- device scratch (no allocations allowed) ----------------
__device__ float g_rot[TAPS];
__device__ float g_gauss[TAPS];
__device__ int   g_lo[2];
__device__ int   g_hi[2];
__device__ float g_mid[N_PIX_MAX];    // after rotational conv
__device__ float g_conv[N_PIX_MAX];   // after gaussian conv
__device__ float g_sums[N_BINS];
__device__ float g_cnts[N_BINS];

// ---------------- zero the bin accumulators (graph replays!) -------------
__global__ void zero_kernel() {
    int i = blockIdx.x * blockDim.x + threadIdx.x;
    int stride = gridDim.x * blockDim.x;
    for (int j = i; j < N_BINS; j += stride) {
        g_sums[j] = 0.0f;
        g_cnts[j] = 0.0f;
    }
}

// ---------------- build both kernels + support bounds on device ----------
__global__ void setup_kernel(const float* __restrict__ ln_sigma,
                             const float* __restrict__ ln_vsini) {
    __shared__ float red[1024];
    __shared__ int s_lo0, s_hi0, s_lo1, s_hi1;
    int tid = threadIdx.x;
    if (tid == 0) { s_lo0 = TAPS; s_hi0 = -1; s_lo1 = TAPS; s_hi1 = -1; }
    __syncthreads();

    float vsini = 0.9f + expf(ln_vsini[0]);
    float sigma = 0.01f + expf(ln_sigma[0]);

    float w  = 0.0f;   // rotational tap (pre-normalization)
    float gw = 0.0f;   // gaussian tap
    if (tid < TAPS) {
        float g = -4.5f + 0.01f * (float)tid;   // linspace(-4.5,4.5,901)
        float x  = (299792.458f * g / 10500.0f) / vsini;
        float x2 = fminf(x * x, 1.0f);
        if (x2 < 0.99999999f) {
            w = 2.0f * sqrtf(1.0f - x2);
            atomicMin(&s_lo0, tid);
            atomicMax(&s_hi0, tid);
        }
        float e = expf(-0.5f * g * g / (sigma * sigma));
        if (e >= 1e-12f) {                       // relative-to-peak cutoff
            atomicMin(&s_lo1, tid);
            atomicMax(&s_hi1, tid);
        }
        gw = (0.01f / (sigma * sqrtf(2.0f * 3.1415926654f))) * e;
    }

    // block sum of rotational kernel for normalization
    red[tid] = w;
    __syncthreads();
    for (int s = 512; s > 0; s >>= 1) {
        if (tid < s) red[tid] += red[tid + s];
        __syncthreads();
    }
    float total = red[0];

    if (tid < TAPS) {
        g_rot[tid]   = w / total;
        g_gauss[tid] = gw;
    }
    if (tid == 0) {
        g_lo[0] = s_lo0; g_hi[0] = s_hi0;
        g_lo[1] = s_lo1; g_hi[1] = s_hi1;
    }
}

// ---------------- tiled 'same' convolution, dynamic tap bounds -----------
// which==0: ext_in --(rot)--> g_mid ; which==1: g_mid --(gauss)--> g_conv
__global__ void __launch_bounds__(CONV_THREADS)
conv_kernel(const float* __restrict__ ext_in, int n, int which) {
    __shared__ float sh[TILE + 2 * HALF];   // 1924 floats
    __shared__ float wsh[TAPS];

    const float* __restrict__ in  = which ? (const float*)g_mid : ext_in;
    float* __restrict__       out = which ? g_conv : g_mid;
    const float* __restrict__ w   = which ? g_gauss : g_rot;
    const int lo = g_lo[which];
    const int hi = g_hi[which];

    const int tile0 = blockIdx.x * TILE;
    const int tid   = threadIdx.x;

    for (int j = tid; j < TAPS; j += CONV_THREADS)
        wsh[j] = w[j];
    for (int j = tid; j < TILE + 2 * HALF; j += CONV_THREADS) {
        int gidx = tile0 - HALF + j;
        sh[j] = (gidx >= 0 && gidx < n) ? in[gidx] : 0.0f;
    }
    __syncthreads();

    float a0 = 0.0f, a1 = 0.0f, a2 = 0.0f, a3 = 0.0f;
    int t = lo;
    for (; t + 3 <= hi; t += 4) {
#pragma unroll
        for (int u = 0; u < 4; ++u) {
            float wv = wsh[t + u];
            int b = tid + t + u;
            a0 = fmaf(sh[b],       wv, a0);
            a1 = fmaf(sh[b + 256], wv, a1);
            a2 = fmaf(sh[b + 512], wv, a2);
            a3 = fmaf(sh[b + 768], wv, a3);
        }
    }
    for (; t <= hi; ++t) {
        float wv = wsh[t];
        int b = tid + t;
        a0 = fmaf(sh[b],       wv, a0);
        a1 = fmaf(sh[b + 256], wv, a1);
        a2 = fmaf(sh[b + 512], wv, a2);
        a3 = fmaf(sh[b + 768], wv, a3);
    }

    int o = tile0 + tid;
    if (o       < n) out[o]       = a0;
    if (o + 256 < n) out[o + 256] = a1;
    if (o + 512 < n) out[o + 512] = a2;
    if (o + 768 < n) out[o + 768] = a3;
}

// ---------------- sorted segment sum/count (run-length + atomics) --------
__global__ void seg_kernel(const int* __restrict__ ids, int n) {
    long long tidg = (long long)(blockIdx.x * blockDim.x + threadIdx.x);
    int base = (int)(tidg * 8);
    if (base >= n) return;
    int end = base + 8;
    if (end > n) end = n;

    int   cur = ids[base];
    float s = 0.0f, c = 0.0f;
    for (int k = base; k < end; ++k) {
        int id = ids[k];
        if (id != cur) {
            atomicAdd(&g_sums[cur], s);
            atomicAdd(&g_cnts[cur], c);
            cur = id; s = 0.0f; c = 0.0f;
        }
        s += g_conv[k];
        c += 1.0f;
    }
    atomicAdd(&g_sums[cur], s);
    atomicAdd(&g_cnts[cur], c);
}

// ---------------- means, clip, drop first/last bin -----------------------
__global__ void final_kernel(float* __restrict__ out, int n_out) {
    int i = blockIdx.x * blockDim.x + threadIdx.x;
    if (i < n_out) {
        int id = i + 1;
        float c = g_cnts[id];
        float m = g_sums[id] / fmaxf(c, 1.0f);
        out[i] = fminf(fmaxf(m, 0.0f), 1.0f);
    }
}

extern "C" void kernel_launch(void* const* d_in, const int* in_sizes, int n_in,
                              void* d_out, int out_size) {
    const float* flux     = (const float*)d_in[0];
    const float* ln_sigma = (const float*)d_in[1];
    const float* ln_vsini = (const float*)d_in[2];
    const int*   ids      = (const int*)d_in[3];
    int n = in_sizes[0];

    zero_kernel<<<684, 512>>>();
    setup_kernel<<<1, 1024>>>(ln_sigma, ln_vsini);

    int conv_blocks = (n + TILE - 1) / TILE;
    conv_kernel<<<conv_blocks, CONV_THREADS>>>(flux, n, 0);
    conv_kernel<<<conv_blocks, CONV_THREADS>>>(flux, n, 1);

    int seg_threads = (n + 7) / 8;
    seg_kernel<<<(seg_threads + 255) / 256, 256>>>(ids, n);

    final_kernel<<<(out_size + 255) / 256, 256>>>((float*)d_out, out_size);
}